// round 10
// baseline (speedup 1.0000x reference)
#include <cuda_runtime.h>
#include <math.h>

#define NT   1000
#define NTP  1024
#define H    128
#define B    1024
#define L    256
#define NPAIR 136               // lower-triangle 64x64 gram tiles
#define NBLK  141               // total blocks (all co-resident on 148 SMs)
#define SMEM_FLOATS 24624
#define SMEM_BYTES (SMEM_FLOATS * 4)
// W_out (517,3) row-major: rows 0:128 venue, 128:256 team, 256:384 opp,
// 384:512 result, 512 gf, 513 ga, 514:517 stats.

// ---- device scratch ----
__device__ float  g_G[NTP * NTP];
__device__ float4 g_PT1[NTP];
__device__ float4 g_PT2[NTP];
__device__ float4 g_PVR[9];
__device__ float  g_Gven[9];
__device__ unsigned int g_bar_count;   // zero-init; returns to 0 each replay

// ---------------------------------------------------------------------------
// Fused kernel, grid = 141, one block per SM (all resident):
//   phase 1: blocks 0..135 gram tile; 136..139 team proj; 140 3x3 tables
//   (main-role blocks 0..127 then issue their stream loads into registers)
//   device-wide barrier
//   phase 2: blocks 0..127 run main (warp-per-batch) out of smem
// ---------------------------------------------------------------------------
__global__ void __launch_bounds__(256) fused_kernel(
    const float* __restrict__ E,
    const float* __restrict__ venue_embed,
    const float* __restrict__ result_embed,
    const float* __restrict__ W,
    const float* __restrict__ b_out,
    const int* __restrict__ venue, const int* __restrict__ team,
    const int* __restrict__ opp,   const int* __restrict__ result,
    const float* __restrict__ gf,  const float* __restrict__ ga,
    const float* __restrict__ stats,
    const int* __restrict__ next_venue, const int* __restrict__ next_team,
    const int* __restrict__ next_opp,
    float* __restrict__ out) {

    extern __shared__ float sm[];
    const int bx   = blockIdx.x;
    const int tid  = threadIdx.x;
    const int lane = tid & 31;
    const int w    = tid >> 5;

    // =============== phase 1: prep ===============
    if (bx < NPAIR) {
        float* As = sm;             // 64 x 68
        float* Bs = sm + 64 * 68;
        const int ti = (int)floorf((sqrtf(8.0f * bx + 1.0f) - 1.0f) * 0.5f + 1e-4f);
        const int tj = bx - ti * (ti + 1) / 2;
        const int i0 = ti * 64;
        const int j0 = tj * 64;
        const int tx = tid & 15;
        const int ty = tid >> 4;

        // preload BOTH k-halves: 16 LDG.128 in flight
        float4 ra[2][4], rb[2][4];
        const float4 z4 = make_float4(0.f, 0.f, 0.f, 0.f);
        #pragma unroll
        for (int h = 0; h < 2; h++) {
            #pragma unroll
            for (int i = 0; i < 4; i++) {
                const int idx = tid + 256 * i;
                const int t  = idx >> 4;
                const int k4 = idx & 15;
                const int ri = i0 + t;
                const int rj = j0 + t;
                ra[h][i] = (ri < NT) ? *(const float4*)(E + ri * H + 64 * h + 4 * k4) : z4;
                rb[h][i] = (rj < NT) ? *(const float4*)(E + rj * H + 64 * h + 4 * k4) : z4;
            }
        }

        unsigned long long accp[4][2];
        #pragma unroll
        for (int u = 0; u < 4; u++) { accp[u][0] = 0ull; accp[u][1] = 0ull; }

        #pragma unroll
        for (int h = 0; h < 2; h++) {
            if (h) __syncthreads();
            #pragma unroll
            for (int i = 0; i < 4; i++) {
                const int idx = tid + 256 * i;
                const int t  = idx >> 4;
                const int k4 = idx & 15;
                const int c  = t ^ (4 * (k4 & 7));
                const int r0 = 4 * k4;
                As[(r0 + 0) * 68 + c] = ra[h][i].x;
                As[(r0 + 1) * 68 + c] = ra[h][i].y;
                As[(r0 + 2) * 68 + c] = ra[h][i].z;
                As[(r0 + 3) * 68 + c] = ra[h][i].w;
                Bs[(r0 + 0) * 68 + c] = rb[h][i].x;
                Bs[(r0 + 1) * 68 + c] = rb[h][i].y;
                Bs[(r0 + 2) * 68 + c] = rb[h][i].z;
                Bs[(r0 + 3) * 68 + c] = rb[h][i].w;
            }
            __syncthreads();

            #pragma unroll 16
            for (int k = 0; k < 64; k++) {
                const int cc = (k >> 2) & 7;
                const float4 a4 = *(const float4*)&As[k * 68 + 4 * (ty ^ cc)];
                const ulonglong2 b2 = *(const ulonglong2*)&Bs[k * 68 + 4 * (tx ^ cc)];
                const unsigned int au[4] = {
                    __float_as_uint(a4.x), __float_as_uint(a4.y),
                    __float_as_uint(a4.z), __float_as_uint(a4.w)};
                #pragma unroll
                for (int u = 0; u < 4; u++) {
                    unsigned long long ap;
                    asm("mov.b64 %0, {%1, %1};" : "=l"(ap) : "r"(au[u]));
                    asm("fma.rn.f32x2 %0, %1, %2, %0;"
                        : "+l"(accp[u][0]) : "l"(ap), "l"(b2.x));
                    asm("fma.rn.f32x2 %0, %1, %2, %0;"
                        : "+l"(accp[u][1]) : "l"(ap), "l"(b2.y));
                }
            }
        }

        float acc[4][4];
        #pragma unroll
        for (int u = 0; u < 4; u++) {
            unsigned int lo, hi;
            asm("mov.b64 {%0, %1}, %2;" : "=r"(lo), "=r"(hi) : "l"(accp[u][0]));
            acc[u][0] = __uint_as_float(lo); acc[u][1] = __uint_as_float(hi);
            asm("mov.b64 {%0, %1}, %2;" : "=r"(lo), "=r"(hi) : "l"(accp[u][1]));
            acc[u][2] = __uint_as_float(lo); acc[u][3] = __uint_as_float(hi);
        }

        float4* G4 = (float4*)g_G;
        #pragma unroll
        for (int u = 0; u < 4; u++) {
            const int i = i0 + 4 * ty + u;
            G4[(i * NTP + j0) / 4 + tx] =
                make_float4(acc[u][0], acc[u][1], acc[u][2], acc[u][3]);
        }
        if (ti != tj) {
            #pragma unroll
            for (int v = 0; v < 4; v++) {
                const int j = j0 + 4 * tx + v;
                G4[(j * NTP + i0) / 4 + ty] =
                    make_float4(acc[0][v], acc[1][v], acc[2][v], acc[3][v]);
            }
        }
    } else if (bx < NPAIR + 4) {
        const int t = (bx - NPAIR) * 256 + tid;
        if (t < NT) {
            const float4* row = (const float4*)(E + t * H);
            float a0 = 0, a1 = 0, a2 = 0, b0 = 0, b1 = 0, b2 = 0;
            #pragma unroll 8
            for (int k4 = 0; k4 < 32; k4++) {
                const float4 e = row[k4];
                const float ev[4] = {e.x, e.y, e.z, e.w};
                #pragma unroll
                for (int d = 0; d < 4; d++) {
                    const int k = 4 * k4 + d;
                    a0 += ev[d] * W[(128 + k) * 3 + 0];
                    a1 += ev[d] * W[(128 + k) * 3 + 1];
                    a2 += ev[d] * W[(128 + k) * 3 + 2];
                    b0 += ev[d] * W[(256 + k) * 3 + 0];
                    b1 += ev[d] * W[(256 + k) * 3 + 1];
                    b2 += ev[d] * W[(256 + k) * 3 + 2];
                }
            }
            g_PT1[t] = make_float4(a0, a1, a2, 0.0f);
            g_PT2[t] = make_float4(b0, b1, b2, 0.0f);
        }
    } else {
        // 3x3 tables: warp per (i,j)
        for (int p = w; p < 9; p += 8) {
            const int i = p / 3, j = p % 3;
            const float4 vi = *(const float4*)(venue_embed  + i * H + 4 * lane);
            const float4 vj = *(const float4*)(venue_embed  + j * H + 4 * lane);
            const float4 re = *(const float4*)(result_embed + j * H + 4 * lane);
            const float4 w0 = *(const float4*)(W + 12 * lane + 0);
            const float4 w1 = *(const float4*)(W + 12 * lane + 4);
            const float4 w2 = *(const float4*)(W + 12 * lane + 8);
            const float4 q0 = *(const float4*)(W + 384 * 3 + 12 * lane + 0);
            const float4 q1 = *(const float4*)(W + 384 * 3 + 12 * lane + 4);
            const float4 q2 = *(const float4*)(W + 384 * 3 + 12 * lane + 8);
            const float viv[4] = {vi.x, vi.y, vi.z, vi.w};
            const float vjv[4] = {vj.x, vj.y, vj.z, vj.w};
            const float rev[4] = {re.x, re.y, re.z, re.w};
            const float wv[12] = {w0.x, w0.y, w0.z, w0.w, w1.x, w1.y, w1.z, w1.w,
                                  w2.x, w2.y, w2.z, w2.w};
            const float qv[12] = {q0.x, q0.y, q0.z, q0.w, q1.x, q1.y, q1.z, q1.w,
                                  q2.x, q2.y, q2.z, q2.w};
            float gv = 0, p0 = 0, p1 = 0, p2 = 0;
            #pragma unroll
            for (int d = 0; d < 4; d++) {
                gv += viv[d] * vjv[d];
                p0 += viv[d] * wv[3 * d + 0] + rev[d] * qv[3 * d + 0];
                p1 += viv[d] * wv[3 * d + 1] + rev[d] * qv[3 * d + 1];
                p2 += viv[d] * wv[3 * d + 2] + rev[d] * qv[3 * d + 2];
            }
            #pragma unroll
            for (int off = 16; off; off >>= 1) {
                gv += __shfl_xor_sync(0xffffffffu, gv, off);
                p0 += __shfl_xor_sync(0xffffffffu, p0, off);
                p1 += __shfl_xor_sync(0xffffffffu, p1, off);
                p2 += __shfl_xor_sync(0xffffffffu, p2, off);
            }
            if (lane == 0) {
                g_Gven[p] = gv;
                g_PVR[p]  = make_float4(p0, p1, p2, 0.0f);
            }
        }
    }

    // =============== pre-barrier main loads (latency hides under barrier) ===
    const int b = bx * 8 + w;
    int nv = 0, nt = 0, no = 0;
    int4  v4a = {0,0,0,0}, t4a = v4a, o4a = v4a, r4a = v4a;
    int4  v4b = v4a, t4b = v4a, o4b = v4a, r4b = v4a;
    float4 gf4a = {0,0,0,0}, ga4a = gf4a, gf4b = gf4a, ga4b = gf4a;
    float wgf0 = 0, wgf1 = 0, wgf2 = 0, wga0 = 0, wga1 = 0, wga2 = 0;
    float st0 = 0, st1 = 0, st2 = 0, bo0 = 0, bo1 = 0, bo2 = 0;
    float ws[9];
    if (bx < 128) {
        nv = next_venue[b]; nt = next_team[b]; no = next_opp[b];
        const int idx0 = b * L + lane * 4;
        const int idx1 = idx0 + 128;
        v4a  = *(const int4*)(venue  + idx0);  v4b  = *(const int4*)(venue  + idx1);
        t4a  = *(const int4*)(team   + idx0);  t4b  = *(const int4*)(team   + idx1);
        o4a  = *(const int4*)(opp    + idx0);  o4b  = *(const int4*)(opp    + idx1);
        r4a  = *(const int4*)(result + idx0);  r4b  = *(const int4*)(result + idx1);
        gf4a = *(const float4*)(gf + idx0);    gf4b = *(const float4*)(gf + idx1);
        ga4a = *(const float4*)(ga + idx0);    ga4b = *(const float4*)(ga + idx1);
        wgf0 = W[512 * 3 + 0]; wgf1 = W[512 * 3 + 1]; wgf2 = W[512 * 3 + 2];
        wga0 = W[513 * 3 + 0]; wga1 = W[513 * 3 + 1]; wga2 = W[513 * 3 + 2];
        if (lane == 0) {
            st0 = stats[b * 3 + 0]; st1 = stats[b * 3 + 1]; st2 = stats[b * 3 + 2];
            bo0 = b_out[0]; bo1 = b_out[1]; bo2 = b_out[2];
            #pragma unroll
            for (int i = 0; i < 9; i++) ws[i] = W[514 * 3 + i];
        }
    }

    // =============== device-wide barrier ===============
    __syncthreads();
    if (tid == 0) {
        __threadfence();
        const unsigned t = atomicAdd(&g_bar_count, 1u);
        if (t == NBLK - 1u) {
            atomicExch(&g_bar_count, 0u);          // release everyone
        } else {
            while (atomicAdd(&g_bar_count, 0u) != 0u) __nanosleep(64);
        }
        __threadfence();
    }
    __syncthreads();

    if (bx >= 128) return;

    // =============== phase 2: main (warp per batch) ===============
    float*  rows  = sm;                      // [8][2][1024]
    float4* PT1s  = (float4*)(sm + 16384);
    float4* PT2s  = (float4*)(sm + 20480);
    float4* PVRs  = (float4*)(sm + 24576);
    float*  Gvens = sm + 24612;

    // stage this warp's two Gram rows (coalesced, L2)
    {
        const float4* src1 = (const float4*)(g_G + nt * NTP);
        const float4* src2 = (const float4*)(g_G + no * NTP);
        float4* dst1 = (float4*)(rows + w * 2048);
        float4* dst2 = (float4*)(rows + w * 2048 + 1024);
        #pragma unroll
        for (int i = 0; i < 8; i++) {
            dst1[lane + 32 * i] = src1[lane + 32 * i];
            dst2[lane + 32 * i] = src2[lane + 32 * i];
        }
    }
    // stage tables (block-cooperative)
    #pragma unroll
    for (int i = 0; i < 4; i++) {
        PT1s[tid + 256 * i] = g_PT1[tid + 256 * i];
        PT2s[tid + 256 * i] = g_PT2[tid + 256 * i];
    }
    if (tid < 9) { PVRs[tid] = g_PVR[tid]; Gvens[tid] = g_Gven[tid]; }

    const int   vv[8]  = {v4a.x, v4a.y, v4a.z, v4a.w, v4b.x, v4b.y, v4b.z, v4b.w};
    const int   tt[8]  = {t4a.x, t4a.y, t4a.z, t4a.w, t4b.x, t4b.y, t4b.z, t4b.w};
    const int   oo[8]  = {o4a.x, o4a.y, o4a.z, o4a.w, o4b.x, o4b.y, o4b.z, o4b.w};
    const int   rr[8]  = {r4a.x, r4a.y, r4a.z, r4a.w, r4b.x, r4b.y, r4b.z, r4b.w};
    const float gfv[8] = {gf4a.x, gf4a.y, gf4a.z, gf4a.w, gf4b.x, gf4b.y, gf4b.z, gf4b.w};
    const float gav[8] = {ga4a.x, ga4a.y, ga4a.z, ga4a.w, ga4b.x, ga4b.y, ga4b.z, ga4b.w};

    __syncthreads();

    const float* rw0 = rows + w * 2048;
    const float* rw1 = rows + w * 2048 + 1024;

    const float inv_scale = 0.051031036307982884f;  // 1/sqrt(384)
    float s[8];
    #pragma unroll
    for (int j = 0; j < 8; j++)
        s[j] = (Gvens[vv[j] * 3 + nv] + rw0[tt[j]] + rw1[oo[j]]) * inv_scale;

    float m = s[0];
    #pragma unroll
    for (int j = 1; j < 8; j++) m = fmaxf(m, s[j]);
    #pragma unroll
    for (int off = 16; off; off >>= 1)
        m = fmaxf(m, __shfl_xor_sync(0xffffffffu, m, off));

    float e[8], su = 0.0f;
    #pragma unroll
    for (int j = 0; j < 8; j++) { e[j] = __expf(s[j] - m); su += e[j]; }
    #pragma unroll
    for (int off = 16; off; off >>= 1)
        su += __shfl_xor_sync(0xffffffffu, su, off);
    const float inv = __frcp_rn(su);

    float c0 = 0, c1 = 0, c2 = 0;
    #pragma unroll
    for (int j = 0; j < 8; j++) {
        const float a = e[j] * inv;
        const float4 p1  = PT1s[tt[j]];
        const float4 p2  = PT2s[oo[j]];
        const float4 pvr = PVRs[vv[j] * 3 + rr[j]];
        c0 += a * (p1.x + p2.x + pvr.x + gfv[j] * wgf0 + gav[j] * wga0);
        c1 += a * (p1.y + p2.y + pvr.y + gfv[j] * wgf1 + gav[j] * wga1);
        c2 += a * (p1.z + p2.z + pvr.z + gfv[j] * wgf2 + gav[j] * wga2);
    }
    #pragma unroll
    for (int off = 16; off; off >>= 1) {
        c0 += __shfl_xor_sync(0xffffffffu, c0, off);
        c1 += __shfl_xor_sync(0xffffffffu, c1, off);
        c2 += __shfl_xor_sync(0xffffffffu, c2, off);
    }

    if (lane == 0) {
        c0 += st0 * ws[0] + st1 * ws[3] + st2 * ws[6] + bo0;
        c1 += st0 * ws[1] + st1 * ws[4] + st2 * ws[7] + bo1;
        c2 += st0 * ws[2] + st1 * ws[5] + st2 * ws[8] + bo2;
        out[b * 3 + 0] = c0;
        out[b * 3 + 1] = c1;
        out[b * 3 + 2] = c2;
    }
}

// ---------------------------------------------------------------------------
extern "C" void kernel_launch(void* const* d_in, const int* in_sizes, int n_in,
                              void* d_out, int out_size) {
    const float* team_embed    = (const float*)d_in[0];
    const float* venue_embed   = (const float*)d_in[1];
    const float* result_embed  = (const float*)d_in[2];
    const float* W_out         = (const float*)d_in[3];
    const float* b_out         = (const float*)d_in[4];
    const float* goals_for     = (const float*)d_in[5];
    const float* goals_against = (const float*)d_in[6];
    const float* stats         = (const float*)d_in[7];
    const int*   venue         = (const int*)d_in[8];
    const int*   team          = (const int*)d_in[9];
    const int*   opponent      = (const int*)d_in[10];
    const int*   result        = (const int*)d_in[11];
    const int*   next_venue    = (const int*)d_in[12];
    const int*   next_team     = (const int*)d_in[13];
    const int*   next_opponent = (const int*)d_in[14];
    float* out = (float*)d_out;

    cudaFuncSetAttribute(fused_kernel,
                         cudaFuncAttributeMaxDynamicSharedMemorySize,
                         SMEM_BYTES);

    fused_kernel<<<NBLK, 256, SMEM_BYTES>>>(
        team_embed, venue_embed, result_embed, W_out, b_out,
        venue, team, opponent, result,
        goals_for, goals_against, stats,
        next_venue, next_team, next_opponent,
        out);
}